// round 9
// baseline (speedup 1.0000x reference)
#include <cuda_runtime.h>
#include <math.h>
#include <stdint.h>

#define BATCH 8
#define NBF   4194304   // 65536*64 floats per batch
typedef unsigned long long u64;

// ---------------- async copy helpers -----------------------------------------
__device__ __forceinline__ void cp16(void* smem, const void* gmem) {
  unsigned s = (unsigned)__cvta_generic_to_shared(smem);
  asm volatile("cp.async.cg.shared.global [%0], [%1], 16;" :: "r"(s), "l"(gmem));
}
__device__ __forceinline__ void cp_commit() { asm volatile("cp.async.commit_group;"); }
template<int N> __device__ __forceinline__ void cp_wait() {
  asm volatile("cp.async.wait_group %0;" :: "n"(N));
}

// ---------------- bf16 mma helpers ---------------------------------------------
__device__ __forceinline__ uint32_t pkb(float lo, float hi) {
  uint32_t r;
  asm("cvt.rn.bf16x2.f32 %0, %1, %2;" : "=r"(r) : "f"(hi), "f"(lo));
  return r;
}
__device__ __forceinline__ void mma16(float* c, const uint32_t* a, const uint32_t* b) {
  asm volatile(
      "mma.sync.aligned.m16n8k16.row.col.f32.bf16.bf16.f32 "
      "{%0,%1,%2,%3}, {%4,%5,%6,%7}, {%8,%9}, {%0,%1,%2,%3};"
      : "+f"(c[0]), "+f"(c[1]), "+f"(c[2]), "+f"(c[3])
      : "r"(a[0]), "r"(a[1]), "r"(a[2]), "r"(a[3]), "r"(b[0]), "r"(b[1]));
}

// ---------------- scratch globals -----------------------------------------------
__device__ float    g_part[BATCH * 128 * 4096];
__device__ float    g_G[BATCH * 4096];
__device__ uint32_t g_MPk[BATCH * 2048];  // M packed bf16x2: [c][ep], pairs along e
__device__ uint32_t g_WpPk[2048];         // Wp^T packed: [c2p][j], pairs along c2

// ---------------- kA: partial G = X^T X (bf16 mma, cp.async 3-buffer) ------------
// 4 launches x 256 blocks x 256 thr. Chunk = 512 rows, 8 stages of 64 rows.
// smem u32 words: raw[3][4352] fp32 (pitch 68) | pk[2][2304] (pitch 72) = 17664 w
// = 70656 B -> 3 blocks/SM. Park (fp32 cross-warp reduce) aliases the raw region.
#define KA_SMEM_BYTES (17664 * 4)
__global__ void __launch_bounds__(256, 3) kA(const float* __restrict__ x, int chunk0) {
  extern __shared__ uint32_t dsm[];
  float* raw = reinterpret_cast<float*>(dsm);   // 3 x 4352 words
  uint32_t* pk = dsm + 13056;                   // 2 x 2304 words
  float* park = reinterpret_cast<float*>(dsm);  // aliases raw (after compute)
  int cid = chunk0 + blockIdx.x;
  int b = cid >> 7, chunk = cid & 127;
  const float* Xc = x + (size_t)b * NBF + (size_t)chunk * 32768;
  int t = threadIdx.x, w = t >> 5, lane = t & 31, g = lane >> 2, t4 = lane & 3;
  int ms = (w & 3) * 16, h = w >> 2;
  int kp = t >> 3, c0 = (t & 7) * 8;
  float acc[8][4];
#pragma unroll
  for (int i = 0; i < 8; i++)
#pragma unroll
    for (int q = 0; q < 4; q++) acc[i][q] = 0.f;

  // prologue: stages 0 and 1 in flight
#pragma unroll
  for (int s = 0; s < 2; s++) {
    const float* src = Xc + s * 4096;
    float* dst = raw + s * 4352;
#pragma unroll
    for (int i = 0; i < 4; i++) {
      int id = i * 256 + t;             // 0..1023: row = id>>4, q = id&15
      cp16(dst + (id >> 4) * 68 + (id & 15) * 4, src + (id >> 4) * 64 + (id & 15) * 4);
    }
    cp_commit();
  }

  for (int s = 0; s < 8; s++) {
    if (s < 7) cp_wait<1>(); else cp_wait<0>();
    __syncthreads();                    // raw(s) visible; pk(s&1) free
    // pack raw(s) -> pk(s&1): pairs along k (rows 2kp, 2kp+1)
    {
      const float* r0 = raw + (s % 3) * 4352 + (2 * kp) * 68 + c0;
      const float* r1 = r0 + 68;
      float4 a0 = *(const float4*)(r0);
      float4 a2 = *(const float4*)(r0 + 4);
      float4 b0 = *(const float4*)(r1);
      float4 b2 = *(const float4*)(r1 + 4);
      uint32_t* dst = pk + (s & 1) * 2304 + kp * 72 + c0;
      *(uint4*)dst = make_uint4(pkb(a0.x, b0.x), pkb(a0.y, b0.y),
                                pkb(a0.z, b0.z), pkb(a0.w, b0.w));
      *(uint4*)(dst + 4) = make_uint4(pkb(a2.x, b2.x), pkb(a2.y, b2.y),
                                      pkb(a2.z, b2.z), pkb(a2.w, b2.w));
    }
    if (s < 6) {                        // issue stage s+2
      const float* src = Xc + (s + 2) * 4096;
      float* dst = raw + ((s + 2) % 3) * 4352;
#pragma unroll
      for (int i = 0; i < 4; i++) {
        int id = i * 256 + t;
        cp16(dst + (id >> 4) * 68 + (id & 15) * 4, src + (id >> 4) * 64 + (id & 15) * 4);
      }
      cp_commit();
    }
    __syncthreads();                    // pk(s) visible
    const uint32_t* B = pk + (s & 1) * 2304;
#pragma unroll
    for (int ki = 0; ki < 2; ki++) {
      int kt = 2 * h + ki;
      const uint32_t* r_lo = B + (kt * 8 + t4) * 72;
      const uint32_t* r_hi = r_lo + 288;
      uint32_t a[4] = { r_lo[ms + g], r_lo[ms + g + 8], r_hi[ms + g], r_hi[ms + g + 8] };
#pragma unroll
      for (int nt = 0; nt < 8; nt++) {
        uint32_t bb[2] = { r_lo[nt * 8 + g], r_hi[nt * 8 + g] };
        mma16(acc[nt], a, bb);
      }
    }
  }
  __syncthreads();
  // park fp32 partials per k-half (raw region now free), then sum to g_part
  float* Ph = park + h * 4608;
#pragma unroll
  for (int nt = 0; nt < 8; nt++) {
    int col = nt * 8 + 2 * t4;
    *(float2*)&Ph[(ms + g) * 72 + col]     = make_float2(acc[nt][0], acc[nt][1]);
    *(float2*)&Ph[(ms + g + 8) * 72 + col] = make_float2(acc[nt][2], acc[nt][3]);
  }
  __syncthreads();
  float* P = g_part + (size_t)cid * 4096;
#pragma unroll
  for (int i = 0; i < 16; i++) {
    int idx = i * 256 + t, r = idx >> 6, c = idx & 63;
    P[idx] = park[r * 72 + c] + park[4608 + r * 72 + c];
  }
}

// ---------------- kRed: reduce 128 partials per batch ----------------------------
__global__ void __launch_bounds__(256) kRed() {
  int b = blockIdx.x >> 4, s = blockIdx.x & 15;
  int e = s * 256 + threadIdx.x;
  const float* P = g_part + (size_t)b * 128 * 4096 + e;
  float sum = 0.f;
#pragma unroll 8
  for (int k = 0; k < 128; k++) sum += P[(size_t)k * 4096];
  g_G[b * 4096 + e] = sum;
}

// ---------------- kB: attn, topk+softmax, M (fp32, exact) ------------------------
__global__ void __launch_bounds__(256) kB(const float* __restrict__ wqkv,
                                          const float* __restrict__ wproj) {
  int b = blockIdx.x, t = threadIdx.x;
  __shared__ __align__(16) float sG[4096];
  __shared__ __align__(16) float sP[4096];
  __shared__ __align__(16) float sW[4096];
  for (int i = t; i < 4096; i += 256) sG[i] = g_G[b * 4096 + i];
  for (int i = t; i < 4096; i += 256) sW[i] = wqkv[4096 + i];  // Wk
  __syncthreads();
  {
    int e = t >> 2, d0 = (t & 3) * 16;
    float acc[16];
#pragma unroll
    for (int i = 0; i < 16; i++) acc[i] = 0.f;
    for (int f = 0; f < 64; f++) {
      float gg = sG[e * 64 + f];
#pragma unroll
      for (int i = 0; i < 16; i++) acc[i] += gg * sW[(d0 + i) * 64 + f];
    }
#pragma unroll
    for (int i = 0; i < 16; i++) sP[e * 64 + d0 + i] = acc[i];
  }
  __syncthreads();
  for (int i = t; i < 4096; i += 256) sW[i] = wqkv[8192 + i];  // Wv
  __syncthreads();
  {
    int c = t >> 2, d0 = (t & 3) * 16;
    float acc[16];
#pragma unroll
    for (int i = 0; i < 16; i++) acc[i] = 0.f;
    for (int e = 0; e < 64; e++) {
      float wv = sW[c * 64 + e];
#pragma unroll
      for (int i = 0; i < 16; i++) acc[i] += wv * sP[e * 64 + d0 + i];
    }
#pragma unroll
    for (int i = 0; i < 16; i++) sG[c * 64 + d0 + i] = acc[i] * 0.125f;
  }
  __syncthreads();
  if (t < 64) {
    float* row = sG + t * 64;
    u64 drop = 0;
    for (int it = 0; it < 14; it++) {
      float mn = INFINITY; int mi = 0;
      for (int d = 0; d < 64; d++) {
        if ((drop >> d) & 1ULL) continue;
        float v = row[d];
        if (v < mn) { mn = v; mi = d; }
      }
      drop |= 1ULL << mi;
    }
    float mx = -INFINITY;
    for (int d = 0; d < 64; d++)
      if (!((drop >> d) & 1ULL)) mx = fmaxf(mx, row[d]);
    float sum = 0.f;
    for (int d = 0; d < 64; d++) {
      float e = ((drop >> d) & 1ULL) ? 0.f : expf(row[d] - mx);
      row[d] = e; sum += e;
    }
    float inv = 1.f / sum;
    for (int d = 0; d < 64; d++) row[d] *= inv;
  }
  __syncthreads();
  for (int i = t; i < 4096; i += 256) sW[i] = wqkv[i];  // Wq
  __syncthreads();
  {
    int c = t >> 2, e0 = (t & 3) * 16;
    float acc[16];
#pragma unroll
    for (int i = 0; i < 16; i++) acc[i] = 0.f;
    for (int d = 0; d < 64; d++) {
      float a = sG[c * 64 + d];
#pragma unroll
      for (int i = 0; i < 16; i++) acc[i] += a * sW[d * 64 + e0 + i];
    }
#pragma unroll
    for (int i = 0; i < 8; i++)
      g_MPk[b * 2048 + c * 32 + (e0 >> 1) + i] = pkb(acc[2 * i], acc[2 * i + 1]);
  }
  if (b == 0) {
    for (int i = t; i < 2048; i += 256) {
      int c2p = i >> 6, j = i & 63;
      g_WpPk[i] = pkb(wproj[j * 64 + 2 * c2p], wproj[j * 64 + 2 * c2p + 1]);
    }
  }
}

// ---------------- kC: per (b,p): Y = M (Xblk^T Wp^T) + bp + x (bf16 mma) ----------
__global__ void __launch_bounds__(256, 3) kC(const float* __restrict__ x,
                                             const float* __restrict__ bproj,
                                             float* __restrict__ y) {
  __shared__ uint32_t sX[2304];    // packed X, later packed D1
  __shared__ uint32_t sWp[2304];
  __shared__ uint32_t sMp[2304];
  int t = threadIdx.x, w = t >> 5, lane = t & 31, g = lane >> 2, t4 = lane & 3;
  int ms = (w & 3) * 16, nh = (w >> 2) * 32;
  int b = blockIdx.x >> 7, grp = blockIdx.x & 127;
  const float* xbase = x + (size_t)b * NBF;
  float* yb = y + (size_t)b * NBF;
  for (int i = t; i < 2048; i += 256) sWp[(i >> 6) * 72 + (i & 63)] = g_WpPk[i];
  for (int i = t; i < 2048; i += 256) sMp[(i >> 5) * 36 + (i & 31)] = g_MPk[b * 2048 + i];
  int kp = t >> 3, c0 = (t & 7) * 8;
  const float* src0 = xbase + (size_t)(grp * 8) * 4096 + kp * 128 + c0;
  float4 p0 = *(const float4*)(src0);
  float4 p1 = *(const float4*)(src0 + 64);
  float4 p2 = *(const float4*)(src0 + 4);
  float4 p3 = *(const float4*)(src0 + 68);

  for (int it = 0; it < 8; it++) {
    int p = grp * 8 + it;
    uint32_t* dst = sX + kp * 72 + c0;
    *(uint4*)dst = make_uint4(pkb(p0.x, p1.x), pkb(p0.y, p1.y),
                              pkb(p0.z, p1.z), pkb(p0.w, p1.w));
    *(uint4*)(dst + 4) = make_uint4(pkb(p2.x, p3.x), pkb(p2.y, p3.y),
                                    pkb(p2.z, p3.z), pkb(p2.w, p3.w));
    __syncthreads();
    if (it < 7) {
      const float* ns = xbase + (size_t)(p + 1) * 4096 + kp * 128 + c0;
      p0 = *(const float4*)(ns);      p1 = *(const float4*)(ns + 64);
      p2 = *(const float4*)(ns + 4);  p3 = *(const float4*)(ns + 68);
      if (t < 128) {
        const float* pf = xbase + (((size_t)(t >> 1) * 1024 + p + 1) << 6) + (t & 1) * 32;
        asm volatile("prefetch.L2 [%0];" :: "l"(pf));
      }
    }
    float acc[4][4];
#pragma unroll
    for (int i = 0; i < 4; i++)
#pragma unroll
      for (int q = 0; q < 4; q++) acc[i][q] = 0.f;
#pragma unroll
    for (int kt = 0; kt < 4; kt++) {
      const uint32_t* a_lo = sX + (kt * 8 + t4) * 72;
      const uint32_t* a_hi = a_lo + 288;
      uint32_t a[4] = { a_lo[ms + g], a_lo[ms + g + 8], a_hi[ms + g], a_hi[ms + g + 8] };
      const uint32_t* b_lo = sWp + (kt * 8 + t4) * 72 + nh;
      const uint32_t* b_hi = b_lo + 288;
#pragma unroll
      for (int nt = 0; nt < 4; nt++) {
        uint32_t bb[2] = { b_lo[nt * 8 + g], b_hi[nt * 8 + g] };
        mma16(acc[nt], a, bb);
      }
    }
    __syncthreads();
#pragma unroll
    for (int nt = 0; nt < 4; nt++) {
      float o0 = __shfl_xor_sync(0xffffffffu, acc[nt][0], 4);
      float o1 = __shfl_xor_sync(0xffffffffu, acc[nt][1], 4);
      float o2 = __shfl_xor_sync(0xffffffffu, acc[nt][2], 4);
      float o3 = __shfl_xor_sync(0xffffffffu, acc[nt][3], 4);
      if (!(g & 1)) {
        int j = nh + nt * 8 + 2 * t4;
        int kp0 = (ms + g) >> 1, kp8 = kp0 + 4;
        sX[kp0 * 72 + j]     = pkb(acc[nt][0], o0);
        sX[kp0 * 72 + j + 1] = pkb(acc[nt][1], o1);
        sX[kp8 * 72 + j]     = pkb(acc[nt][2], o2);
        sX[kp8 * 72 + j + 1] = pkb(acc[nt][3], o3);
      }
    }
    __syncthreads();
    float oc[4][4];
#pragma unroll
    for (int i = 0; i < 4; i++)
#pragma unroll
      for (int q = 0; q < 4; q++) oc[i][q] = 0.f;
#pragma unroll
    for (int kt = 0; kt < 4; kt++) {
      const uint32_t* r0 = sMp + (ms + g) * 36 + kt * 8;
      const uint32_t* r1 = r0 + 8 * 36;
      uint32_t a[4] = { r0[t4], r1[t4], r0[t4 + 4], r1[t4 + 4] };
      const uint32_t* b_lo = sX + (kt * 8 + t4) * 72 + nh;
      const uint32_t* b_hi = b_lo + 288;
#pragma unroll
      for (int nt = 0; nt < 4; nt++) {
        uint32_t bb[2] = { b_lo[nt * 8 + g], b_hi[nt * 8 + g] };
        mma16(oc[nt], a, bb);
      }
    }
#pragma unroll
    for (int nt = 0; nt < 4; nt++) {
      int j0 = nh + nt * 8 + 2 * t4;
      float2 bp = *(const float2*)(bproj + j0);
      int cr0 = ms + g, cr1 = ms + g + 8;
      size_t off0 = ((size_t)(cr0 * 1024 + p) << 6) + j0;
      size_t off1 = ((size_t)(cr1 * 1024 + p) << 6) + j0;
      float2 x0 = *(const float2*)(xbase + off0);
      float2 x1 = *(const float2*)(xbase + off1);
      *(float2*)(yb + off0) = make_float2(oc[nt][0] + bp.x + x0.x, oc[nt][1] + bp.y + x0.y);
      *(float2*)(yb + off1) = make_float2(oc[nt][2] + bp.x + x1.x, oc[nt][3] + bp.y + x1.y);
    }
    __syncthreads();
  }
}

extern "C" void kernel_launch(void* const* d_in, const int* in_sizes, int n_in,
                              void* d_out, int out_size) {
  const float* x     = (const float*)d_in[0];
  const float* wqkv  = (const float*)d_in[1];
  const float* wproj = (const float*)d_in[2];
  const float* bproj = (const float*)d_in[3];
  float* y = (float*)d_out;
  static int smem_set = 0;
  if (!smem_set) {
    cudaFuncSetAttribute(kA, cudaFuncAttributeMaxDynamicSharedMemorySize,
                         KA_SMEM_BYTES);
    smem_set = 1;
  }
  // 7 launches/iter: capture index {3,15} -> {kA piece 3, kA piece 1} either way
  kA<<<256, 256, KA_SMEM_BYTES>>>(x, 0);
  kA<<<256, 256, KA_SMEM_BYTES>>>(x, 256);
  kA<<<256, 256, KA_SMEM_BYTES>>>(x, 512);
  kA<<<256, 256, KA_SMEM_BYTES>>>(x, 768);
  kRed<<<128, 256>>>();
  kB<<<8, 256>>>(wqkv, wproj);
  kC<<<1024, 256>>>(x, bproj, y);
}

// round 10
// speedup vs baseline: 1.0694x; 1.0694x over previous
#include <cuda_runtime.h>
#include <math.h>
#include <stdint.h>

#define BATCH 8
#define NBF   4194304   // 65536*64 floats per batch
typedef unsigned long long u64;

// ---------------- async copy helpers -----------------------------------------
__device__ __forceinline__ void cp16(void* smem, const void* gmem) {
  unsigned s = (unsigned)__cvta_generic_to_shared(smem);
  asm volatile("cp.async.cg.shared.global [%0], [%1], 16;" :: "r"(s), "l"(gmem));
}
__device__ __forceinline__ void cp_commit() { asm volatile("cp.async.commit_group;"); }
template<int N> __device__ __forceinline__ void cp_wait() {
  asm volatile("cp.async.wait_group %0;" :: "n"(N));
}

// ---------------- bf16 mma helpers ---------------------------------------------
__device__ __forceinline__ uint32_t pkb(float lo, float hi) {
  uint32_t r;
  asm("cvt.rn.bf16x2.f32 %0, %1, %2;" : "=r"(r) : "f"(hi), "f"(lo));
  return r;
}
__device__ __forceinline__ void mma16(float* c, const uint32_t* a, const uint32_t* b) {
  asm volatile(
      "mma.sync.aligned.m16n8k16.row.col.f32.bf16.bf16.f32 "
      "{%0,%1,%2,%3}, {%4,%5,%6,%7}, {%8,%9}, {%0,%1,%2,%3};"
      : "+f"(c[0]), "+f"(c[1]), "+f"(c[2]), "+f"(c[3])
      : "r"(a[0]), "r"(a[1]), "r"(a[2]), "r"(a[3]), "r"(b[0]), "r"(b[1]));
}

// ---------------- scratch globals -----------------------------------------------
__device__ float    g_part[BATCH * 128 * 4096];
__device__ float    g_G[BATCH * 4096];
__device__ uint32_t g_MPk[BATCH * 2048];  // M packed bf16x2: [c][ep], pairs along e
__device__ uint32_t g_WpPk[2048];         // Wp^T packed: [c2p][j], pairs along c2

// ---------------- kA: partial G = X^T X (bf16 mma, cp.async 3-buffer) ------------
// 1024 blocks x 256 thr. Chunk = 512 rows, 8 stages of 64 rows.
// smem u32 words: raw[3][4352] fp32 (pitch 68) | pk[2][2304] (pitch 72) = 17664 w
// = 70656 B -> 3 blocks/SM. Park (fp32 cross-warp reduce) aliases the raw region.
#define KA_SMEM_BYTES (17664 * 4)
__global__ void __launch_bounds__(256, 3) kA(const float* __restrict__ x) {
  extern __shared__ uint32_t dsm[];
  float* raw = reinterpret_cast<float*>(dsm);   // 3 x 4352 words
  uint32_t* pk = dsm + 13056;                   // 2 x 2304 words
  float* park = reinterpret_cast<float*>(dsm);  // aliases raw (after compute)
  int cid = blockIdx.x;
  int b = cid >> 7, chunk = cid & 127;
  const float* Xc = x + (size_t)b * NBF + (size_t)chunk * 32768;
  int t = threadIdx.x, w = t >> 5, lane = t & 31, g = lane >> 2, t4 = lane & 3;
  int ms = (w & 3) * 16, h = w >> 2;
  int kp = t >> 3, c0 = (t & 7) * 8;
  float acc[8][4];
#pragma unroll
  for (int i = 0; i < 8; i++)
#pragma unroll
    for (int q = 0; q < 4; q++) acc[i][q] = 0.f;

  // prologue: stages 0 and 1 in flight
#pragma unroll
  for (int s = 0; s < 2; s++) {
    const float* src = Xc + s * 4096;
    float* dst = raw + s * 4352;
#pragma unroll
    for (int i = 0; i < 4; i++) {
      int id = i * 256 + t;
      cp16(dst + (id >> 4) * 68 + (id & 15) * 4, src + (id >> 4) * 64 + (id & 15) * 4);
    }
    cp_commit();
  }

  for (int s = 0; s < 8; s++) {
    if (s < 7) cp_wait<1>(); else cp_wait<0>();
    __syncthreads();                    // raw(s) visible; pk(s&1) free
    {
      const float* r0 = raw + (s % 3) * 4352 + (2 * kp) * 68 + c0;
      const float* r1 = r0 + 68;
      float4 a0 = *(const float4*)(r0);
      float4 a2 = *(const float4*)(r0 + 4);
      float4 b0 = *(const float4*)(r1);
      float4 b2 = *(const float4*)(r1 + 4);
      uint32_t* dst = pk + (s & 1) * 2304 + kp * 72 + c0;
      *(uint4*)dst = make_uint4(pkb(a0.x, b0.x), pkb(a0.y, b0.y),
                                pkb(a0.z, b0.z), pkb(a0.w, b0.w));
      *(uint4*)(dst + 4) = make_uint4(pkb(a2.x, b2.x), pkb(a2.y, b2.y),
                                      pkb(a2.z, b2.z), pkb(a2.w, b2.w));
    }
    if (s < 6) {
      const float* src = Xc + (s + 2) * 4096;
      float* dst = raw + ((s + 2) % 3) * 4352;
#pragma unroll
      for (int i = 0; i < 4; i++) {
        int id = i * 256 + t;
        cp16(dst + (id >> 4) * 68 + (id & 15) * 4, src + (id >> 4) * 64 + (id & 15) * 4);
      }
      cp_commit();
    }
    __syncthreads();                    // pk(s) visible
    const uint32_t* B = pk + (s & 1) * 2304;
#pragma unroll
    for (int ki = 0; ki < 2; ki++) {
      int kt = 2 * h + ki;
      const uint32_t* r_lo = B + (kt * 8 + t4) * 72;
      const uint32_t* r_hi = r_lo + 288;
      uint32_t a[4] = { r_lo[ms + g], r_lo[ms + g + 8], r_hi[ms + g], r_hi[ms + g + 8] };
#pragma unroll
      for (int nt = 0; nt < 8; nt++) {
        uint32_t bb[2] = { r_lo[nt * 8 + g], r_hi[nt * 8 + g] };
        mma16(acc[nt], a, bb);
      }
    }
  }
  __syncthreads();
  float* Ph = park + h * 4608;
#pragma unroll
  for (int nt = 0; nt < 8; nt++) {
    int col = nt * 8 + 2 * t4;
    *(float2*)&Ph[(ms + g) * 72 + col]     = make_float2(acc[nt][0], acc[nt][1]);
    *(float2*)&Ph[(ms + g + 8) * 72 + col] = make_float2(acc[nt][2], acc[nt][3]);
  }
  __syncthreads();
  float* P = g_part + (size_t)cid * 4096;
#pragma unroll
  for (int i = 0; i < 16; i++) {
    int idx = i * 256 + t, r = idx >> 6, c = idx & 63;
    P[idx] = park[r * 72 + c] + park[4608 + r * 72 + c];
  }
}

// ---------------- kRed: reduce 128 partials per batch ----------------------------
__global__ void __launch_bounds__(256) kRed() {
  int b = blockIdx.x >> 4, s = blockIdx.x & 15;
  int e = s * 256 + threadIdx.x;
  const float* P = g_part + (size_t)b * 128 * 4096 + e;
  float sum = 0.f;
#pragma unroll 8
  for (int k = 0; k < 128; k++) sum += P[(size_t)k * 4096];
  g_G[b * 4096 + e] = sum;
}

// ---------------- kB: attn, topk+softmax, M (fp32, exact) ------------------------
__global__ void __launch_bounds__(256) kB(const float* __restrict__ wqkv,
                                          const float* __restrict__ wproj) {
  int b = blockIdx.x, t = threadIdx.x;
  __shared__ __align__(16) float sG[4096];
  __shared__ __align__(16) float sP[4096];
  __shared__ __align__(16) float sW[4096];
  for (int i = t; i < 4096; i += 256) sG[i] = g_G[b * 4096 + i];
  for (int i = t; i < 4096; i += 256) sW[i] = wqkv[4096 + i];  // Wk
  __syncthreads();
  {
    int e = t >> 2, d0 = (t & 3) * 16;
    float acc[16];
#pragma unroll
    for (int i = 0; i < 16; i++) acc[i] = 0.f;
    for (int f = 0; f < 64; f++) {
      float gg = sG[e * 64 + f];
#pragma unroll
      for (int i = 0; i < 16; i++) acc[i] += gg * sW[(d0 + i) * 64 + f];
    }
#pragma unroll
    for (int i = 0; i < 16; i++) sP[e * 64 + d0 + i] = acc[i];
  }
  __syncthreads();
  for (int i = t; i < 4096; i += 256) sW[i] = wqkv[8192 + i];  // Wv
  __syncthreads();
  {
    int c = t >> 2, d0 = (t & 3) * 16;
    float acc[16];
#pragma unroll
    for (int i = 0; i < 16; i++) acc[i] = 0.f;
    for (int e = 0; e < 64; e++) {
      float wv = sW[c * 64 + e];
#pragma unroll
      for (int i = 0; i < 16; i++) acc[i] += wv * sP[e * 64 + d0 + i];
    }
#pragma unroll
    for (int i = 0; i < 16; i++) sG[c * 64 + d0 + i] = acc[i] * 0.125f;
  }
  __syncthreads();
  if (t < 64) {
    float* row = sG + t * 64;
    u64 drop = 0;
    for (int it = 0; it < 14; it++) {
      float mn = INFINITY; int mi = 0;
      for (int d = 0; d < 64; d++) {
        if ((drop >> d) & 1ULL) continue;
        float v = row[d];
        if (v < mn) { mn = v; mi = d; }
      }
      drop |= 1ULL << mi;
    }
    float mx = -INFINITY;
    for (int d = 0; d < 64; d++)
      if (!((drop >> d) & 1ULL)) mx = fmaxf(mx, row[d]);
    float sum = 0.f;
    for (int d = 0; d < 64; d++) {
      float e = ((drop >> d) & 1ULL) ? 0.f : expf(row[d] - mx);
      row[d] = e; sum += e;
    }
    float inv = 1.f / sum;
    for (int d = 0; d < 64; d++) row[d] *= inv;
  }
  __syncthreads();
  for (int i = t; i < 4096; i += 256) sW[i] = wqkv[i];  // Wq
  __syncthreads();
  {
    int c = t >> 2, e0 = (t & 3) * 16;
    float acc[16];
#pragma unroll
    for (int i = 0; i < 16; i++) acc[i] = 0.f;
    for (int d = 0; d < 64; d++) {
      float a = sG[c * 64 + d];
#pragma unroll
      for (int i = 0; i < 16; i++) acc[i] += a * sW[d * 64 + e0 + i];
    }
#pragma unroll
    for (int i = 0; i < 8; i++)
      g_MPk[b * 2048 + c * 32 + (e0 >> 1) + i] = pkb(acc[2 * i], acc[2 * i + 1]);
  }
  if (b == 0) {
    for (int i = t; i < 2048; i += 256) {
      int c2p = i >> 6, j = i & 63;
      g_WpPk[i] = pkb(wproj[j * 64 + 2 * c2p], wproj[j * 64 + 2 * c2p + 1]);
    }
  }
}

// ---------------- kC: per (b,p): Y = M (Xblk^T Wp^T) + bp + x (bf16 mma) ----------
// 1024 blocks x 256 thr; 8 p-tiles per block; 8 warps = 4 m-slices x 2 n-halves.
// Double-buffered packed X + separate D1 buffer -> 2 barriers per tile.
// static smem: 5 x 2304 u32 = 46080 B -> 3 blocks/SM (opt-in not needed, <48 KB).
__global__ void __launch_bounds__(256, 3) kC(const float* __restrict__ x,
                                             const float* __restrict__ bproj,
                                             float* __restrict__ y) {
  __shared__ uint32_t sX[2][2304];
  __shared__ uint32_t sD1[2304];
  __shared__ uint32_t sWp[2304];
  __shared__ uint32_t sMp[2304];
  int t = threadIdx.x, w = t >> 5, lane = t & 31, g = lane >> 2, t4 = lane & 3;
  int ms = (w & 3) * 16, nh = (w >> 2) * 32;
  int b = blockIdx.x >> 7, grp = blockIdx.x & 127;
  const float* xbase = x + (size_t)b * NBF;
  float* yb = y + (size_t)b * NBF;
  for (int i = t; i < 2048; i += 256) sWp[(i >> 6) * 72 + (i & 63)] = g_WpPk[i];
  for (int i = t; i < 2048; i += 256) sMp[(i >> 5) * 36 + (i & 31)] = g_MPk[b * 2048 + i];
  int kp = t >> 3, c0 = (t & 7) * 8;
  // pack tile 0, then prefetch tile 1 into regs
  float4 p0, p1, p2, p3;
  {
    const float* s0 = xbase + (size_t)(grp * 8) * 4096 + kp * 128 + c0;
    p0 = *(const float4*)(s0);      p1 = *(const float4*)(s0 + 64);
    p2 = *(const float4*)(s0 + 4);  p3 = *(const float4*)(s0 + 68);
    uint32_t* dst = sX[0] + kp * 72 + c0;
    *(uint4*)dst = make_uint4(pkb(p0.x, p1.x), pkb(p0.y, p1.y),
                              pkb(p0.z, p1.z), pkb(p0.w, p1.w));
    *(uint4*)(dst + 4) = make_uint4(pkb(p2.x, p3.x), pkb(p2.y, p3.y),
                                    pkb(p2.z, p3.z), pkb(p2.w, p3.w));
    const float* s1 = s0 + 4096;
    p0 = *(const float4*)(s1);      p1 = *(const float4*)(s1 + 64);
    p2 = *(const float4*)(s1 + 4);  p3 = *(const float4*)(s1 + 68);
  }

  for (int it = 0; it < 8; it++) {
    int p = grp * 8 + it;
    __syncthreads();                   // sX[it&1] packed; sD1 free (prev GEMM2 done)
    // GEMM1: D1[e,j] = sum_c2 X[c2,e] * WpT[c2,j]
    float acc[4][4];
#pragma unroll
    for (int i = 0; i < 4; i++)
#pragma unroll
      for (int q = 0; q < 4; q++) acc[i][q] = 0.f;
    const uint32_t* Xb = sX[it & 1];
#pragma unroll
    for (int kt = 0; kt < 4; kt++) {
      const uint32_t* a_lo = Xb + (kt * 8 + t4) * 72;
      const uint32_t* a_hi = a_lo + 288;
      uint32_t a[4] = { a_lo[ms + g], a_lo[ms + g + 8], a_hi[ms + g], a_hi[ms + g + 8] };
      const uint32_t* b_lo = sWp + (kt * 8 + t4) * 72 + nh;
      const uint32_t* b_hi = b_lo + 288;
#pragma unroll
      for (int nt = 0; nt < 4; nt++) {
        uint32_t bb[2] = { b_lo[nt * 8 + g], b_hi[nt * 8 + g] };
        mma16(acc[nt], a, bb);
      }
    }
    // overlap: pack next tile (other buffer) + load regs for tile it+2
    if (it < 7) {
      uint32_t* dst = sX[(it + 1) & 1] + kp * 72 + c0;
      *(uint4*)dst = make_uint4(pkb(p0.x, p1.x), pkb(p0.y, p1.y),
                                pkb(p0.z, p1.z), pkb(p0.w, p1.w));
      *(uint4*)(dst + 4) = make_uint4(pkb(p2.x, p3.x), pkb(p2.y, p3.y),
                                      pkb(p2.z, p3.z), pkb(p2.w, p3.w));
      if (it < 6) {
        const float* ns = xbase + (size_t)(p + 2) * 4096 + kp * 128 + c0;
        p0 = *(const float4*)(ns);      p1 = *(const float4*)(ns + 64);
        p2 = *(const float4*)(ns + 4);  p3 = *(const float4*)(ns + 68);
      }
      if (t < 128) {  // L2 prefetch next residual rows
        const float* pf = xbase + (((size_t)(t >> 1) * 1024 + p + 1) << 6) + (t & 1) * 32;
        asm volatile("prefetch.L2 [%0];" :: "l"(pf));
      }
    }
    // pack D1 -> sD1 (pairs along e via lane-pair shuffle); even-g lanes store
#pragma unroll
    for (int nt = 0; nt < 4; nt++) {
      float o0 = __shfl_xor_sync(0xffffffffu, acc[nt][0], 4);
      float o1 = __shfl_xor_sync(0xffffffffu, acc[nt][1], 4);
      float o2 = __shfl_xor_sync(0xffffffffu, acc[nt][2], 4);
      float o3 = __shfl_xor_sync(0xffffffffu, acc[nt][3], 4);
      if (!(g & 1)) {
        int j = nh + nt * 8 + 2 * t4;
        int kp0 = (ms + g) >> 1, kp8 = kp0 + 4;
        sD1[kp0 * 72 + j]     = pkb(acc[nt][0], o0);
        sD1[kp0 * 72 + j + 1] = pkb(acc[nt][1], o1);
        sD1[kp8 * 72 + j]     = pkb(acc[nt][2], o2);
        sD1[kp8 * 72 + j + 1] = pkb(acc[nt][3], o3);
      }
    }
    __syncthreads();                   // sD1 ready
    // GEMM2: OUT[c,j] = sum_e M[c,e] * D1[e,j]
    float oc[4][4];
#pragma unroll
    for (int i = 0; i < 4; i++)
#pragma unroll
      for (int q = 0; q < 4; q++) oc[i][q] = 0.f;
#pragma unroll
    for (int kt = 0; kt < 4; kt++) {
      const uint32_t* r0 = sMp + (ms + g) * 36 + kt * 8;
      const uint32_t* r1 = r0 + 8 * 36;
      uint32_t a[4] = { r0[t4], r1[t4], r0[t4 + 4], r1[t4 + 4] };
      const uint32_t* b_lo = sD1 + (kt * 8 + t4) * 72 + nh;
      const uint32_t* b_hi = b_lo + 288;
#pragma unroll
      for (int nt = 0; nt < 4; nt++) {
        uint32_t bb[2] = { b_lo[nt * 8 + g], b_hi[nt * 8 + g] };
        mma16(oc[nt], a, bb);
      }
    }
    // epilogue: y = OUT + bp + x
#pragma unroll
    for (int nt = 0; nt < 4; nt++) {
      int j0 = nh + nt * 8 + 2 * t4;
      float2 bp = *(const float2*)(bproj + j0);
      int cr0 = ms + g, cr1 = ms + g + 8;
      size_t off0 = ((size_t)(cr0 * 1024 + p) << 6) + j0;
      size_t off1 = ((size_t)(cr1 * 1024 + p) << 6) + j0;
      float2 x0 = *(const float2*)(xbase + off0);
      float2 x1 = *(const float2*)(xbase + off1);
      *(float2*)(yb + off0) = make_float2(oc[nt][0] + bp.x + x0.x, oc[nt][1] + bp.y + x0.y);
      *(float2*)(yb + off1) = make_float2(oc[nt][2] + bp.x + x1.x, oc[nt][3] + bp.y + x1.y);
    }
  }
}

extern "C" void kernel_launch(void* const* d_in, const int* in_sizes, int n_in,
                              void* d_out, int out_size) {
  const float* x     = (const float*)d_in[0];
  const float* wqkv  = (const float*)d_in[1];
  const float* wproj = (const float*)d_in[2];
  const float* bproj = (const float*)d_in[3];
  float* y = (float*)d_out;
  static int smem_set = 0;
  if (!smem_set) {
    cudaFuncSetAttribute(kA, cudaFuncAttributeMaxDynamicSharedMemorySize,
                         KA_SMEM_BYTES);
    smem_set = 1;
  }
  kA<<<1024, 256, KA_SMEM_BYTES>>>(x);
  kRed<<<128, 256>>>();
  kB<<<8, 256>>>(wqkv, wproj);
  kC<<<1024, 256>>>(x, bproj, y);
}